// round 15
// baseline (speedup 1.0000x reference)
#include <cuda_runtime.h>
#include <math.h>

#define NN 4096
#define MM 4096
#define DD 64
#define W_EPS 0.1f
#define INV_EPS 10.0f
#define ITERS 10
#define RPS 128
#define SLABS (NN / RPS)            // 32  (exact col pass, iter 1)

#define FS 8                        // fused slab rows
#define FSLABS (NN / FS)            // 512 fused slabs

#define CT_STRIDE 132
#define CT_KH 32

// ------------- static device scratch -------------
__device__ float d_C[(size_t)NN * MM];
__device__ float d_f[NN];
__device__ float d_g[MM];
__device__ float d_nx[NN];
__device__ float d_ny[MM];
__device__ float d_pm[SLABS * MM];
__device__ float d_ps[SLABS * MM];
__device__ float d_colsum[(size_t)FSLABS * MM];   // 8 MB fused column partial sums
__device__ double d_parts[2048];

// ------------- online-LSE helpers -------------
__device__ __forceinline__ void lse_merge(float& m1, float& s1, float m2, float s2) {
    float d = (m2 - m1) * INV_EPS;
    float e = __expf(-fabsf(d));
    if (d > 0.0f) { s1 = fmaf(s1, e, s2); m1 = m2; }
    else          { s1 = fmaf(s2, e, s1); }
}
__device__ __forceinline__ void lse_upd1(float& m, float& s, float v) {
    float d = (v - m) * INV_EPS;
    float e = __expf(-fabsf(d));
    bool up = d > 0.0f;
    s = up ? fmaf(s, e, 1.0f) : (s + e);
    m = up ? v : m;
}
__device__ __forceinline__ float4 f4sub(float4 a, float4 b) {
    return make_float4(a.x - b.x, a.y - b.y, a.z - b.z, a.w - b.w);
}
__device__ __forceinline__ float f4max(float4 a) {
    return fmaxf(fmaxf(a.x, a.y), fmaxf(a.z, a.w));
}
__device__ __forceinline__ float f4expsum(float4 a, float mn) {
    return __expf((a.x - mn) * INV_EPS) + __expf((a.y - mn) * INV_EPS)
         + __expf((a.z - mn) * INV_EPS) + __expf((a.w - mn) * INV_EPS);
}

// ================= prep: norms + g = 0 =================
__global__ void k_prep(const float* __restrict__ x, const float* __restrict__ y) {
    int gtid = blockIdx.x * 256 + threadIdx.x;
    if (gtid < MM) d_g[gtid] = 0.0f;
    int lane = threadIdx.x & 31;
    int row = gtid >> 5;
    const float* src = (row < NN) ? (x + (size_t)row * DD)
                                  : (y + (size_t)(row - NN) * DD);
    float a = src[lane], c = src[lane + 32];
    float s = a * a + c * c;
    #pragma unroll
    for (int o = 16; o; o >>= 1) s += __shfl_xor_sync(0xffffffffu, s, o);
    if (lane == 0) { if (row < NN) d_nx[row] = s; else d_ny[row - NN] = s; }
}

// ====== cost: C = nx + ny - 2 x.y (128x128 tile, split 8x8 micro, 2-phase K) ======
__global__ void __launch_bounds__(256)
k_cost(const float* __restrict__ x, const float* __restrict__ y) {
    __shared__ float xs[CT_KH * CT_STRIDE];
    __shared__ float ys[CT_KH * CT_STRIDE];
    const int t = threadIdx.x;
    const int tx = t & 15, ty = t >> 4;
    const int rowBase = blockIdx.y * 128, colBase = blockIdx.x * 128;

    float acc[8][8];
    #pragma unroll
    for (int r = 0; r < 8; r++)
        #pragma unroll
        for (int c = 0; c < 8; c++) acc[r][c] = 0.0f;

    #pragma unroll
    for (int ph = 0; ph < 2; ph++) {
        if (ph) __syncthreads();
        #pragma unroll
        for (int k2 = 0; k2 < 4; k2++) {
            int idx = t + 256 * k2;
            int rid = idx >> 3;
            int d4 = (idx & 7) << 2;
            float4 v = *(const float4*)(x + (size_t)(rowBase + rid) * DD + ph * CT_KH + d4);
            xs[(d4 + 0) * CT_STRIDE + rid] = v.x;
            xs[(d4 + 1) * CT_STRIDE + rid] = v.y;
            xs[(d4 + 2) * CT_STRIDE + rid] = v.z;
            xs[(d4 + 3) * CT_STRIDE + rid] = v.w;
        }
        #pragma unroll
        for (int k2 = 0; k2 < 4; k2++) {
            int idx = t + 256 * k2;
            int cid = idx >> 3;
            int d4 = (idx & 7) << 2;
            float4 v = *(const float4*)(y + (size_t)(colBase + cid) * DD + ph * CT_KH + d4);
            ys[(d4 + 0) * CT_STRIDE + cid] = v.x;
            ys[(d4 + 1) * CT_STRIDE + cid] = v.y;
            ys[(d4 + 2) * CT_STRIDE + cid] = v.z;
            ys[(d4 + 3) * CT_STRIDE + cid] = v.w;
        }
        __syncthreads();

        #pragma unroll 8
        for (int d = 0; d < CT_KH; d++) {
            const float* xr = xs + d * CT_STRIDE;
            const float* yc = ys + d * CT_STRIDE;
            float4 a0 = *(const float4*)(xr + (ty << 2));
            float4 a1 = *(const float4*)(xr + (ty << 2) + 64);
            float4 b0 = *(const float4*)(yc + (tx << 2));
            float4 b1 = *(const float4*)(yc + (tx << 2) + 64);
            float av[8] = {a0.x, a0.y, a0.z, a0.w, a1.x, a1.y, a1.z, a1.w};
            float bv[8] = {b0.x, b0.y, b0.z, b0.w, b1.x, b1.y, b1.z, b1.w};
            #pragma unroll
            for (int r = 0; r < 8; r++)
                #pragma unroll
                for (int c = 0; c < 8; c++)
                    acc[r][c] = fmaf(av[r], bv[c], acc[r][c]);
        }
    }

    float4 nyA = *(const float4*)(d_ny + colBase + (tx << 2));
    float4 nyB = *(const float4*)(d_ny + colBase + (tx << 2) + 64);
    #pragma unroll
    for (int rg = 0; rg < 2; rg++) {
        #pragma unroll
        for (int r4 = 0; r4 < 4; r4++) {
            int r = rg * 4 + r4;
            int row = rowBase + (ty << 2) + rg * 64 + r4;
            float nxr = d_nx[row];
            float4 oA, oB;
            oA.x = nxr + nyA.x - 2.0f * acc[r][0];
            oA.y = nxr + nyA.y - 2.0f * acc[r][1];
            oA.z = nxr + nyA.z - 2.0f * acc[r][2];
            oA.w = nxr + nyA.w - 2.0f * acc[r][3];
            oB.x = nxr + nyB.x - 2.0f * acc[r][4];
            oB.y = nxr + nyB.y - 2.0f * acc[r][5];
            oB.z = nxr + nyB.z - 2.0f * acc[r][6];
            oB.w = nxr + nyB.w - 2.0f * acc[r][7];
            float* dst = d_C + (size_t)row * MM + colBase + (tx << 2);
            *(float4*)dst = oA;
            *(float4*)(dst + 64) = oB;
        }
    }
}

// ====== iter-1 exact kernels (unchanged from 375us base) ======
__global__ void __launch_bounds__(256)
k_row(const float* __restrict__ p) {
    __shared__ float s_pm[16], s_ps[16];
    const int t = threadIdx.x;
    const int lane = t & 31;
    const int warp = t >> 5;
    const int r0 = blockIdx.x * 2;
    const float* C0 = d_C + (size_t)r0 * MM;
    const float* C1 = C0 + MM;

    float4 v0[4], v1[4];
    #pragma unroll
    for (int w = 0; w < 4; w++) {
        int j = (t + 256 * w) * 4;
        float4 g4 = *(const float4*)(d_g + j);
        float4 c0 = *(const float4*)(C0 + j);
        float4 c1 = *(const float4*)(C1 + j);
        v0[w] = f4sub(g4, c0);
        v1[w] = f4sub(g4, c1);
    }
    float m0 = fmaxf(fmaxf(f4max(v0[0]), f4max(v0[1])), fmaxf(f4max(v0[2]), f4max(v0[3])));
    float m1 = fmaxf(fmaxf(f4max(v1[0]), f4max(v1[1])), fmaxf(f4max(v1[2]), f4max(v1[3])));
    float s0 = f4expsum(v0[0], m0) + f4expsum(v0[1], m0) + f4expsum(v0[2], m0) + f4expsum(v0[3], m0);
    float s1 = f4expsum(v1[0], m1) + f4expsum(v1[1], m1) + f4expsum(v1[2], m1) + f4expsum(v1[3], m1);

    #pragma unroll
    for (int o = 16; o; o >>= 1) {
        float mo = __shfl_down_sync(0xffffffffu, m0, o);
        float so = __shfl_down_sync(0xffffffffu, s0, o);
        lse_merge(m0, s0, mo, so);
        mo = __shfl_down_sync(0xffffffffu, m1, o);
        so = __shfl_down_sync(0xffffffffu, s1, o);
        lse_merge(m1, s1, mo, so);
    }
    if (lane == 0) {
        s_pm[warp] = m0;     s_ps[warp] = s0;
        s_pm[8 + warp] = m1; s_ps[8 + warp] = s1;
    }
    __syncthreads();
    if (warp == 0) {
        float mm = s_pm[lane & 15], ss = s_ps[lane & 15];
        #pragma unroll
        for (int o = 4; o; o >>= 1) {
            float mo = __shfl_down_sync(0xffffffffu, mm, o, 8);
            float so = __shfl_down_sync(0xffffffffu, ss, o, 8);
            lse_merge(mm, ss, mo, so);
        }
        if (lane == 0) d_f[r0]     = W_EPS * __logf(p[r0])     - mm - W_EPS * __logf(ss);
        if (lane == 8) d_f[r0 + 1] = W_EPS * __logf(p[r0 + 1]) - mm - W_EPS * __logf(ss);
    }
}

__global__ void __launch_bounds__(256)
k_colpart() {
    const int lane = threadIdx.x & 31;
    const int warp = threadIdx.x >> 5;
    const int u = blockIdx.x * 8 + warp;
    const int slab = u >> 7;
    const int col = ((u & 127) << 5) + lane;
    const float* Cp = d_C + (size_t)slab * RPS * MM + col;
    const float* fp = d_f + slab * RPS;

    float m0 = -3.4e38f, s0 = 0.0f, m1 = -3.4e38f, s1 = 0.0f;
    float m2 = -3.4e38f, s2 = 0.0f, m3 = -3.4e38f, s3 = 0.0f;
    #pragma unroll 8
    for (int k = 0; k < RPS / 4; k++) {
        int r = k * 4;
        float c0 = Cp[(size_t)(r + 0) * MM];
        float c1 = Cp[(size_t)(r + 1) * MM];
        float c2 = Cp[(size_t)(r + 2) * MM];
        float c3 = Cp[(size_t)(r + 3) * MM];
        lse_upd1(m0, s0, fp[r + 0] - c0);
        lse_upd1(m1, s1, fp[r + 1] - c1);
        lse_upd1(m2, s2, fp[r + 2] - c2);
        lse_upd1(m3, s3, fp[r + 3] - c3);
    }
    lse_merge(m0, s0, m1, s1);
    lse_merge(m2, s2, m3, s3);
    lse_merge(m0, s0, m2, s2);
    d_pm[slab * MM + col] = m0;
    d_ps[slab * MM + col] = s0;
}

__global__ void __launch_bounds__(256)
k_colfin(const float* __restrict__ q) {
    int j = blockIdx.x * 256 + threadIdx.x;
    float m0 = -3.4e38f, s0 = 0.0f, m1 = -3.4e38f, s1 = 0.0f;
    float m2 = -3.4e38f, s2 = 0.0f, m3 = -3.4e38f, s3 = 0.0f;
    #pragma unroll
    for (int k = 0; k < SLABS / 4; k++) {
        int k4 = k * 4;
        lse_merge(m0, s0, d_pm[(k4 + 0) * MM + j], d_ps[(k4 + 0) * MM + j]);
        lse_merge(m1, s1, d_pm[(k4 + 1) * MM + j], d_ps[(k4 + 1) * MM + j]);
        lse_merge(m2, s2, d_pm[(k4 + 2) * MM + j], d_ps[(k4 + 2) * MM + j]);
        lse_merge(m3, s3, d_pm[(k4 + 3) * MM + j], d_ps[(k4 + 3) * MM + j]);
    }
    lse_merge(m0, s0, m1, s1);
    lse_merge(m2, s2, m3, s3);
    lse_merge(m0, s0, m2, s2);
    d_g[j] = W_EPS * __logf(q[j]) - m0 - W_EPS * __logf(s0);
}

// ====== fused row+col sweep v2 (iters 2..10): ONE pass over C ======
// FS=8 rows per block, ONE row per step (low reg pressure -> 4 blocks/SM),
// 512 blocks -> <1 wave. Column contribution p_i*e_ij/S_i accumulated in regs.
__global__ void __launch_bounds__(256, 4)
k_rowcol(const float* __restrict__ p) {
    __shared__ float gs[MM];                 // 16 KB staged g
    __shared__ float rm[8], rs[8];
    const int t = threadIdx.x;
    const int lane = t & 31;
    const int warp = t >> 5;
    const int rbase = blockIdx.x * FS;

    #pragma unroll
    for (int k = 0; k < 4; k++) {
        int j = (t + 256 * k) * 4;
        *(float4*)(gs + j) = *(const float4*)(d_g + j);
    }
    __syncthreads();

    float acc[16];
    #pragma unroll
    for (int k = 0; k < 16; k++) acc[k] = 0.0f;

    for (int r = 0; r < FS; r++) {
        const float* Cr = d_C + (size_t)(rbase + r) * MM;
        float e[16];
        float ml = -3.4e38f;
        #pragma unroll
        for (int w = 0; w < 4; w++) {
            int j = (t + 256 * w) * 4;
            float4 g4 = *(const float4*)(gs + j);
            float4 c4 = *(const float4*)(Cr + j);
            float4 a = f4sub(g4, c4);
            e[4 * w + 0] = a.x; e[4 * w + 1] = a.y;
            e[4 * w + 2] = a.z; e[4 * w + 3] = a.w;
            ml = fmaxf(ml, f4max(a));
        }
        float sl = 0.0f;
        #pragma unroll
        for (int k = 0; k < 16; k++) {
            e[k] = __expf((e[k] - ml) * INV_EPS);
            sl += e[k];
        }
        // butterfly: all lanes end with warp (m,s)
        float m = ml, s = sl;
        #pragma unroll
        for (int o = 16; o; o >>= 1) {
            float mo = __shfl_xor_sync(0xffffffffu, m, o);
            float so = __shfl_xor_sync(0xffffffffu, s, o);
            lse_merge(m, s, mo, so);
        }
        if (lane == 0) { rm[warp] = m; rs[warp] = s; }
        __syncthreads();
        // every thread merges the 8 warp results (broadcast reads)
        float M = rm[0], S = rs[0];
        #pragma unroll
        for (int k = 1; k < 8; k++) lse_merge(M, S, rm[k], rs[k]);
        float pr = __ldg(p + rbase + r);
        if (t == 0)
            d_f[rbase + r] = W_EPS * __logf(pr) - M - W_EPS * __logf(S);
        float sc = pr * __expf((ml - M) * INV_EPS) / S;
        #pragma unroll
        for (int k = 0; k < 16; k++) acc[k] = fmaf(sc, e[k], acc[k]);
        __syncthreads();   // WAR on rm/rs
    }

    float* dst = d_colsum + (size_t)blockIdx.x * MM;
    #pragma unroll
    for (int w = 0; w < 4; w++) {
        int j = (t + 256 * w) * 4;
        *(float4*)(dst + j) = make_float4(acc[4 * w + 0], acc[4 * w + 1],
                                          acc[4 * w + 2], acc[4 * w + 3]);
    }
}

// colfin for fused iters: g_new = eps*logq + g_old - eps*log(sum_slabs A)
__global__ void __launch_bounds__(256)
k_colfin2(const float* __restrict__ q) {
    int j = blockIdx.x * 256 + threadIdx.x;   // 16 blocks
    float a0 = 0.0f, a1 = 0.0f, a2 = 0.0f, a3 = 0.0f;
    #pragma unroll 8
    for (int s = 0; s < FSLABS; s += 4) {
        a0 += d_colsum[(size_t)(s + 0) * MM + j];
        a1 += d_colsum[(size_t)(s + 1) * MM + j];
        a2 += d_colsum[(size_t)(s + 2) * MM + j];
        a3 += d_colsum[(size_t)(s + 3) * MM + j];
    }
    float A = (a0 + a1) + (a2 + a3);
    d_g[j] = W_EPS * __logf(q[j]) + d_g[j] - W_EPS * __logf(A);
}

// ================= final: P = exp(S), cost partials =================
__global__ void __launch_bounds__(256)
k_final(float* __restrict__ Pout, int writeP) {
    __shared__ double dred[8];
    const int gsz = 2048 * 256;
    const int gtid = blockIdx.x * 256 + threadIdx.x;
    const int NV4 = (NN * MM) / 4;
    double csum = 0.0;
    #pragma unroll 4
    for (int v4 = gtid; v4 < NV4; v4 += gsz) {
        int base = v4 * 4;
        int i = base >> 12;
        int j = base & (MM - 1);
        float4 c4 = *(const float4*)(d_C + (size_t)base);
        float fi = d_f[i];
        float4 g4 = *(const float4*)(d_g + j);
        float p0 = __expf((fi + g4.x - c4.x) * INV_EPS);
        float p1 = __expf((fi + g4.y - c4.y) * INV_EPS);
        float p2 = __expf((fi + g4.z - c4.z) * INV_EPS);
        float p3 = __expf((fi + g4.w - c4.w) * INV_EPS);
        if (writeP) {
            Pout[base + 0] = p0; Pout[base + 1] = p1;
            Pout[base + 2] = p2; Pout[base + 3] = p3;
        }
        csum += (double)(p0 * c4.x + p1 * c4.y + p2 * c4.z + p3 * c4.w);
    }
    #pragma unroll
    for (int o = 16; o; o >>= 1) csum += __shfl_xor_sync(0xffffffffu, csum, o);
    if ((threadIdx.x & 31) == 0) dred[threadIdx.x >> 5] = csum;
    __syncthreads();
    if (threadIdx.x == 0) {
        double sb = 0.0;
        #pragma unroll
        for (int k2 = 0; k2 < 8; k2++) sb += dred[k2];
        d_parts[blockIdx.x] = sb;
    }
}

__global__ void k_costfin(float* __restrict__ costslot) {
    __shared__ double fin[256];
    int t = threadIdx.x;
    double s = 0.0;
    for (int k2 = t; k2 < 2048; k2 += 256) s += d_parts[k2];
    fin[t] = s;
    __syncthreads();
    if (t == 0) {
        double tot = 0.0;
        for (int k2 = 0; k2 < 256; k2++) tot += fin[k2];
        costslot[0] = (float)tot;
    }
}

// ================= host launch =================
extern "C" void kernel_launch(void* const* d_in, const int* in_sizes, int n_in,
                              void* d_out, int out_size) {
    const float* x = (const float*)d_in[0];
    const float* y = (const float*)d_in[1];
    const float* p = (const float*)d_in[2];
    const float* q = (const float*)d_in[3];
    (void)in_sizes; (void)n_in;

    float* out = (float*)d_out;
    float* costslot = nullptr;
    float* Pout = nullptr;
    const long long total = (long long)NN * MM;
    if ((long long)out_size >= total + 1) { costslot = out; Pout = out + 1; }
    else if ((long long)out_size >= total) { Pout = out; }
    else { costslot = out; }

    k_prep<<<1024, 256>>>(x, y);
    k_cost<<<dim3(MM / 128, NN / 128), 256>>>(x, y);

    // iteration 1: exact two-pass (g = 0 -> fused column sum can underflow)
    k_row<<<NN / 2, 256>>>(p);
    k_colpart<<<512, 256>>>();
    k_colfin<<<16, 256>>>(q);

    // iterations 2..10: fused single-sweep v2
    for (int it = 1; it < ITERS; it++) {
        k_rowcol<<<FSLABS, 256>>>(p);
        k_colfin2<<<16, 256>>>(q);
    }

    k_final<<<2048, 256>>>(Pout, Pout != nullptr);
    if (costslot) k_costfin<<<1, 256>>>(costslot);
}

// round 16
// speedup vs baseline: 1.2932x; 1.2932x over previous
#include <cuda_runtime.h>
#include <math.h>

#define NN 4096
#define MM 4096
#define DD 64
#define W_EPS 0.1f
#define INV_EPS 10.0f
#define ITERS 10
#define RPS 128
#define SLABS (NN / RPS)            // 32

#define CT_STRIDE 132
#define CT_KH 32

// ------------- static device scratch -------------
__device__ float d_C[(size_t)NN * MM];
__device__ float d_f[NN];
__device__ float d_g[MM];
__device__ float d_nx[NN];
__device__ float d_ny[MM];
__device__ float d_pm[SLABS * MM];
__device__ float d_ps[SLABS * MM];
__device__ double d_parts[2048];

// ------------- online-LSE helpers -------------
__device__ __forceinline__ void lse_merge(float& m1, float& s1, float m2, float s2) {
    float d = (m2 - m1) * INV_EPS;
    float e = __expf(-fabsf(d));
    if (d > 0.0f) { s1 = fmaf(s1, e, s2); m1 = m2; }
    else          { s1 = fmaf(s2, e, s1); }
}
__device__ __forceinline__ void lse_upd1(float& m, float& s, float v) {
    float d = (v - m) * INV_EPS;
    float e = __expf(-fabsf(d));
    bool up = d > 0.0f;
    s = up ? fmaf(s, e, 1.0f) : (s + e);
    m = up ? v : m;
}
__device__ __forceinline__ float4 f4sub(float4 a, float4 b) {
    return make_float4(a.x - b.x, a.y - b.y, a.z - b.z, a.w - b.w);
}
__device__ __forceinline__ float f4max(float4 a) {
    return fmaxf(fmaxf(a.x, a.y), fmaxf(a.z, a.w));
}
__device__ __forceinline__ float f4expsum(float4 a, float mn) {
    return __expf((a.x - mn) * INV_EPS) + __expf((a.y - mn) * INV_EPS)
         + __expf((a.z - mn) * INV_EPS) + __expf((a.w - mn) * INV_EPS);
}

// ================= prep: norms + g = 0 =================
__global__ void k_prep(const float* __restrict__ x, const float* __restrict__ y) {
    int gtid = blockIdx.x * 256 + threadIdx.x;
    if (gtid < MM) d_g[gtid] = 0.0f;
    int lane = threadIdx.x & 31;
    int row = gtid >> 5;
    const float* src = (row < NN) ? (x + (size_t)row * DD)
                                  : (y + (size_t)(row - NN) * DD);
    float a = src[lane], c = src[lane + 32];
    float s = a * a + c * c;
    #pragma unroll
    for (int o = 16; o; o >>= 1) s += __shfl_xor_sync(0xffffffffu, s, o);
    if (lane == 0) { if (row < NN) d_nx[row] = s; else d_ny[row - NN] = s; }
}

// ====== cost: C = nx + ny - 2 x.y (128x128 tile, split 8x8 micro, 2-phase K) ======
__global__ void __launch_bounds__(256)
k_cost(const float* __restrict__ x, const float* __restrict__ y) {
    __shared__ float xs[CT_KH * CT_STRIDE];
    __shared__ float ys[CT_KH * CT_STRIDE];
    const int t = threadIdx.x;
    const int tx = t & 15, ty = t >> 4;
    const int rowBase = blockIdx.y * 128, colBase = blockIdx.x * 128;

    float acc[8][8];
    #pragma unroll
    for (int r = 0; r < 8; r++)
        #pragma unroll
        for (int c = 0; c < 8; c++) acc[r][c] = 0.0f;

    #pragma unroll
    for (int ph = 0; ph < 2; ph++) {
        if (ph) __syncthreads();
        #pragma unroll
        for (int k2 = 0; k2 < 4; k2++) {
            int idx = t + 256 * k2;
            int rid = idx >> 3;
            int d4 = (idx & 7) << 2;
            float4 v = *(const float4*)(x + (size_t)(rowBase + rid) * DD + ph * CT_KH + d4);
            xs[(d4 + 0) * CT_STRIDE + rid] = v.x;
            xs[(d4 + 1) * CT_STRIDE + rid] = v.y;
            xs[(d4 + 2) * CT_STRIDE + rid] = v.z;
            xs[(d4 + 3) * CT_STRIDE + rid] = v.w;
        }
        #pragma unroll
        for (int k2 = 0; k2 < 4; k2++) {
            int idx = t + 256 * k2;
            int cid = idx >> 3;
            int d4 = (idx & 7) << 2;
            float4 v = *(const float4*)(y + (size_t)(colBase + cid) * DD + ph * CT_KH + d4);
            ys[(d4 + 0) * CT_STRIDE + cid] = v.x;
            ys[(d4 + 1) * CT_STRIDE + cid] = v.y;
            ys[(d4 + 2) * CT_STRIDE + cid] = v.z;
            ys[(d4 + 3) * CT_STRIDE + cid] = v.w;
        }
        __syncthreads();

        #pragma unroll 8
        for (int d = 0; d < CT_KH; d++) {
            const float* xr = xs + d * CT_STRIDE;
            const float* yc = ys + d * CT_STRIDE;
            float4 a0 = *(const float4*)(xr + (ty << 2));
            float4 a1 = *(const float4*)(xr + (ty << 2) + 64);
            float4 b0 = *(const float4*)(yc + (tx << 2));
            float4 b1 = *(const float4*)(yc + (tx << 2) + 64);
            float av[8] = {a0.x, a0.y, a0.z, a0.w, a1.x, a1.y, a1.z, a1.w};
            float bv[8] = {b0.x, b0.y, b0.z, b0.w, b1.x, b1.y, b1.z, b1.w};
            #pragma unroll
            for (int r = 0; r < 8; r++)
                #pragma unroll
                for (int c = 0; c < 8; c++)
                    acc[r][c] = fmaf(av[r], bv[c], acc[r][c]);
        }
    }

    float4 nyA = *(const float4*)(d_ny + colBase + (tx << 2));
    float4 nyB = *(const float4*)(d_ny + colBase + (tx << 2) + 64);
    #pragma unroll
    for (int rg = 0; rg < 2; rg++) {
        #pragma unroll
        for (int r4 = 0; r4 < 4; r4++) {
            int r = rg * 4 + r4;
            int row = rowBase + (ty << 2) + rg * 64 + r4;
            float nxr = d_nx[row];
            float4 oA, oB;
            oA.x = nxr + nyA.x - 2.0f * acc[r][0];
            oA.y = nxr + nyA.y - 2.0f * acc[r][1];
            oA.z = nxr + nyA.z - 2.0f * acc[r][2];
            oA.w = nxr + nyA.w - 2.0f * acc[r][3];
            oB.x = nxr + nyB.x - 2.0f * acc[r][4];
            oB.y = nxr + nyB.y - 2.0f * acc[r][5];
            oB.z = nxr + nyB.z - 2.0f * acc[r][6];
            oB.w = nxr + nyB.w - 2.0f * acc[r][7];
            float* dst = d_C + (size_t)row * MM + colBase + (tx << 2);
            *(float4*)dst = oA;
            *(float4*)(dst + 64) = oB;
        }
    }
}

// ================= row pass: 2 rows per block, register-resident exact LSE =================
__global__ void __launch_bounds__(256)
k_row(const float* __restrict__ p) {
    __shared__ float s_pm[16], s_ps[16];
    const int t = threadIdx.x;
    const int lane = t & 31;
    const int warp = t >> 5;
    const int r0 = blockIdx.x * 2;
    const float* C0 = d_C + (size_t)r0 * MM;
    const float* C1 = C0 + MM;

    float4 v0[4], v1[4];
    #pragma unroll
    for (int w = 0; w < 4; w++) {
        int j = (t + 256 * w) * 4;
        float4 g4 = *(const float4*)(d_g + j);
        float4 c0 = *(const float4*)(C0 + j);
        float4 c1 = *(const float4*)(C1 + j);
        v0[w] = f4sub(g4, c0);
        v1[w] = f4sub(g4, c1);
    }
    float m0 = fmaxf(fmaxf(f4max(v0[0]), f4max(v0[1])), fmaxf(f4max(v0[2]), f4max(v0[3])));
    float m1 = fmaxf(fmaxf(f4max(v1[0]), f4max(v1[1])), fmaxf(f4max(v1[2]), f4max(v1[3])));
    float s0 = f4expsum(v0[0], m0) + f4expsum(v0[1], m0) + f4expsum(v0[2], m0) + f4expsum(v0[3], m0);
    float s1 = f4expsum(v1[0], m1) + f4expsum(v1[1], m1) + f4expsum(v1[2], m1) + f4expsum(v1[3], m1);

    #pragma unroll
    for (int o = 16; o; o >>= 1) {
        float mo = __shfl_down_sync(0xffffffffu, m0, o);
        float so = __shfl_down_sync(0xffffffffu, s0, o);
        lse_merge(m0, s0, mo, so);
        mo = __shfl_down_sync(0xffffffffu, m1, o);
        so = __shfl_down_sync(0xffffffffu, s1, o);
        lse_merge(m1, s1, mo, so);
    }
    if (lane == 0) {
        s_pm[warp] = m0;     s_ps[warp] = s0;
        s_pm[8 + warp] = m1; s_ps[8 + warp] = s1;
    }
    __syncthreads();
    if (warp == 0) {
        float mm = s_pm[lane & 15], ss = s_ps[lane & 15];
        #pragma unroll
        for (int o = 4; o; o >>= 1) {
            float mo = __shfl_down_sync(0xffffffffu, mm, o, 8);
            float so = __shfl_down_sync(0xffffffffu, ss, o, 8);
            lse_merge(mm, ss, mo, so);
        }
        if (lane == 0) d_f[r0]     = W_EPS * __logf(p[r0])     - mm - W_EPS * __logf(ss);
        if (lane == 8) d_f[r0 + 1] = W_EPS * __logf(p[r0 + 1]) - mm - W_EPS * __logf(ss);
    }
}

// ====== exact column pass (iteration 1 only: g=0 -> needs max tracking) ======
__global__ void __launch_bounds__(256)
k_colpart() {
    const int lane = threadIdx.x & 31;
    const int warp = threadIdx.x >> 5;
    const int u = blockIdx.x * 8 + warp;
    const int slab = u >> 7;
    const int col = ((u & 127) << 5) + lane;
    const float* Cp = d_C + (size_t)slab * RPS * MM + col;
    const float* fp = d_f + slab * RPS;

    float m0 = -3.4e38f, s0 = 0.0f, m1 = -3.4e38f, s1 = 0.0f;
    float m2 = -3.4e38f, s2 = 0.0f, m3 = -3.4e38f, s3 = 0.0f;
    #pragma unroll 8
    for (int k = 0; k < RPS / 4; k++) {
        int r = k * 4;
        float c0 = Cp[(size_t)(r + 0) * MM];
        float c1 = Cp[(size_t)(r + 1) * MM];
        float c2 = Cp[(size_t)(r + 2) * MM];
        float c3 = Cp[(size_t)(r + 3) * MM];
        lse_upd1(m0, s0, fp[r + 0] - c0);
        lse_upd1(m1, s1, fp[r + 1] - c1);
        lse_upd1(m2, s2, fp[r + 2] - c2);
        lse_upd1(m3, s3, fp[r + 3] - c3);
    }
    lse_merge(m0, s0, m1, s1);
    lse_merge(m2, s2, m3, s3);
    lse_merge(m0, s0, m2, s2);
    d_pm[slab * MM + col] = m0;
    d_ps[slab * MM + col] = s0;
}

__global__ void __launch_bounds__(256)
k_colfin(const float* __restrict__ q) {
    int j = blockIdx.x * 256 + threadIdx.x;
    float m0 = -3.4e38f, s0 = 0.0f, m1 = -3.4e38f, s1 = 0.0f;
    float m2 = -3.4e38f, s2 = 0.0f, m3 = -3.4e38f, s3 = 0.0f;
    #pragma unroll
    for (int k = 0; k < SLABS / 4; k++) {
        int k4 = k * 4;
        lse_merge(m0, s0, d_pm[(k4 + 0) * MM + j], d_ps[(k4 + 0) * MM + j]);
        lse_merge(m1, s1, d_pm[(k4 + 1) * MM + j], d_ps[(k4 + 1) * MM + j]);
        lse_merge(m2, s2, d_pm[(k4 + 2) * MM + j], d_ps[(k4 + 2) * MM + j]);
        lse_merge(m3, s3, d_pm[(k4 + 3) * MM + j], d_ps[(k4 + 3) * MM + j]);
    }
    lse_merge(m0, s0, m1, s1);
    lse_merge(m2, s2, m3, s3);
    lse_merge(m0, s0, m2, s2);
    d_g[j] = W_EPS * __logf(q[j]) - m0 - W_EPS * __logf(s0);
}

// ====== plain-sum column pass (iterations 2..10): A_j terms in (0,1] ======
// a += exp((f_i + g_j - C_ij)/eps). Carried dependency per chain = one FADD.
__global__ void __launch_bounds__(256)
k_colsum() {
    const int lane = threadIdx.x & 31;
    const int warp = threadIdx.x >> 5;
    const int u = blockIdx.x * 8 + warp;     // 512 blocks * 8 warps = 4096 units
    const int slab = u >> 7;
    const int col = ((u & 127) << 5) + lane;
    const float* Cp = d_C + (size_t)slab * RPS * MM + col;
    const float* fp = d_f + slab * RPS;
    const float gj = d_g[col];

    float a0 = 0.0f, a1 = 0.0f, a2 = 0.0f, a3 = 0.0f;
    #pragma unroll 8
    for (int k = 0; k < RPS / 4; k++) {
        int r = k * 4;
        float c0 = Cp[(size_t)(r + 0) * MM];
        float c1 = Cp[(size_t)(r + 1) * MM];
        float c2 = Cp[(size_t)(r + 2) * MM];
        float c3 = Cp[(size_t)(r + 3) * MM];
        a0 += __expf((fp[r + 0] + gj - c0) * INV_EPS);
        a1 += __expf((fp[r + 1] + gj - c1) * INV_EPS);
        a2 += __expf((fp[r + 2] + gj - c2) * INV_EPS);
        a3 += __expf((fp[r + 3] + gj - c3) * INV_EPS);
    }
    d_ps[slab * MM + col] = (a0 + a1) + (a2 + a3);
}

// finalize for plain-sum iters: g_new = eps*logq + g_old - eps*log(sum A)
__global__ void __launch_bounds__(256)
k_colfin2(const float* __restrict__ q) {
    int j = blockIdx.x * 256 + threadIdx.x;   // 16 blocks
    float a0 = 0.0f, a1 = 0.0f, a2 = 0.0f, a3 = 0.0f;
    #pragma unroll
    for (int k = 0; k < SLABS / 4; k++) {
        int k4 = k * 4;
        a0 += d_ps[(k4 + 0) * MM + j];
        a1 += d_ps[(k4 + 1) * MM + j];
        a2 += d_ps[(k4 + 2) * MM + j];
        a3 += d_ps[(k4 + 3) * MM + j];
    }
    float A = (a0 + a1) + (a2 + a3);
    d_g[j] = W_EPS * __logf(q[j]) + d_g[j] - W_EPS * __logf(A);
}

// ================= final: P = exp(S), cost partials =================
__global__ void __launch_bounds__(256)
k_final(float* __restrict__ Pout, int writeP) {
    __shared__ double dred[8];
    const int gsz = 2048 * 256;
    const int gtid = blockIdx.x * 256 + threadIdx.x;
    const int NV4 = (NN * MM) / 4;
    double csum = 0.0;
    #pragma unroll 4
    for (int v4 = gtid; v4 < NV4; v4 += gsz) {
        int base = v4 * 4;
        int i = base >> 12;
        int j = base & (MM - 1);
        float4 c4 = *(const float4*)(d_C + (size_t)base);
        float fi = d_f[i];
        float4 g4 = *(const float4*)(d_g + j);
        float p0 = __expf((fi + g4.x - c4.x) * INV_EPS);
        float p1 = __expf((fi + g4.y - c4.y) * INV_EPS);
        float p2 = __expf((fi + g4.z - c4.z) * INV_EPS);
        float p3 = __expf((fi + g4.w - c4.w) * INV_EPS);
        if (writeP) {
            Pout[base + 0] = p0; Pout[base + 1] = p1;
            Pout[base + 2] = p2; Pout[base + 3] = p3;
        }
        csum += (double)(p0 * c4.x + p1 * c4.y + p2 * c4.z + p3 * c4.w);
    }
    #pragma unroll
    for (int o = 16; o; o >>= 1) csum += __shfl_xor_sync(0xffffffffu, csum, o);
    if ((threadIdx.x & 31) == 0) dred[threadIdx.x >> 5] = csum;
    __syncthreads();
    if (threadIdx.x == 0) {
        double sb = 0.0;
        #pragma unroll
        for (int k2 = 0; k2 < 8; k2++) sb += dred[k2];
        d_parts[blockIdx.x] = sb;
    }
}

__global__ void k_costfin(float* __restrict__ costslot) {
    __shared__ double fin[256];
    int t = threadIdx.x;
    double s = 0.0;
    for (int k2 = t; k2 < 2048; k2 += 256) s += d_parts[k2];
    fin[t] = s;
    __syncthreads();
    if (t == 0) {
        double tot = 0.0;
        for (int k2 = 0; k2 < 256; k2++) tot += fin[k2];
        costslot[0] = (float)tot;
    }
}

// ================= host launch =================
extern "C" void kernel_launch(void* const* d_in, const int* in_sizes, int n_in,
                              void* d_out, int out_size) {
    const float* x = (const float*)d_in[0];
    const float* y = (const float*)d_in[1];
    const float* p = (const float*)d_in[2];
    const float* q = (const float*)d_in[3];
    (void)in_sizes; (void)n_in;

    float* out = (float*)d_out;
    float* costslot = nullptr;
    float* Pout = nullptr;
    const long long total = (long long)NN * MM;
    if ((long long)out_size >= total + 1) { costslot = out; Pout = out + 1; }
    else if ((long long)out_size >= total) { Pout = out; }
    else { costslot = out; }

    k_prep<<<1024, 256>>>(x, y);
    k_cost<<<dim3(MM / 128, NN / 128), 256>>>(x, y);

    // iteration 1: exact LSE column pass (g = 0 -> shifted sums can underflow)
    k_row<<<NN / 2, 256>>>(p);
    k_colpart<<<512, 256>>>();
    k_colfin<<<16, 256>>>(q);

    // iterations 2..10: plain-sum column pass
    for (int it = 1; it < ITERS; it++) {
        k_row<<<NN / 2, 256>>>(p);
        k_colsum<<<512, 256>>>();
        k_colfin2<<<16, 256>>>(q);
    }

    k_final<<<2048, 256>>>(Pout, Pout != nullptr);
    if (costslot) k_costfin<<<1, 256>>>(costslot);
}

// round 17
// speedup vs baseline: 1.3697x; 1.0591x over previous
#include <cuda_runtime.h>
#include <math.h>

#define NN 4096
#define MM 4096
#define DD 64
#define W_EPS 0.1f
#define INV_EPS 10.0f
#define ITERS 10
#define RPS 128
#define SLABS (NN / RPS)            // 32

#define CT_STRIDE 132
#define CT_KH 32

// ------------- static device scratch -------------
__device__ float d_C[(size_t)NN * MM];
__device__ float d_f[NN];
__device__ float d_g[MM];
__device__ float d_nx[NN];
__device__ float d_ny[MM];
__device__ float d_pm[SLABS * MM];
__device__ float d_ps[SLABS * MM];
__device__ double d_parts[2048];

// ------------- online-LSE helpers (iteration 1 only) -------------
__device__ __forceinline__ void lse_merge(float& m1, float& s1, float m2, float s2) {
    float d = (m2 - m1) * INV_EPS;
    float e = __expf(-fabsf(d));
    if (d > 0.0f) { s1 = fmaf(s1, e, s2); m1 = m2; }
    else          { s1 = fmaf(s2, e, s1); }
}
__device__ __forceinline__ void lse_upd1(float& m, float& s, float v) {
    float d = (v - m) * INV_EPS;
    float e = __expf(-fabsf(d));
    bool up = d > 0.0f;
    s = up ? fmaf(s, e, 1.0f) : (s + e);
    m = up ? v : m;
}
__device__ __forceinline__ float4 f4sub(float4 a, float4 b) {
    return make_float4(a.x - b.x, a.y - b.y, a.z - b.z, a.w - b.w);
}
__device__ __forceinline__ float f4max(float4 a) {
    return fmaxf(fmaxf(a.x, a.y), fmaxf(a.z, a.w));
}
__device__ __forceinline__ float f4expsum(float4 a, float mn) {
    return __expf((a.x - mn) * INV_EPS) + __expf((a.y - mn) * INV_EPS)
         + __expf((a.z - mn) * INV_EPS) + __expf((a.w - mn) * INV_EPS);
}

// ================= prep: norms + g = 0 =================
__global__ void k_prep(const float* __restrict__ x, const float* __restrict__ y) {
    int gtid = blockIdx.x * 256 + threadIdx.x;
    if (gtid < MM) d_g[gtid] = 0.0f;
    int lane = threadIdx.x & 31;
    int row = gtid >> 5;
    const float* src = (row < NN) ? (x + (size_t)row * DD)
                                  : (y + (size_t)(row - NN) * DD);
    float a = src[lane], c = src[lane + 32];
    float s = a * a + c * c;
    #pragma unroll
    for (int o = 16; o; o >>= 1) s += __shfl_xor_sync(0xffffffffu, s, o);
    if (lane == 0) { if (row < NN) d_nx[row] = s; else d_ny[row - NN] = s; }
}

// ====== cost: C = nx + ny - 2 x.y (128x128 tile, split 8x8 micro, 2-phase K) ======
__global__ void __launch_bounds__(256)
k_cost(const float* __restrict__ x, const float* __restrict__ y) {
    __shared__ float xs[CT_KH * CT_STRIDE];
    __shared__ float ys[CT_KH * CT_STRIDE];
    const int t = threadIdx.x;
    const int tx = t & 15, ty = t >> 4;
    const int rowBase = blockIdx.y * 128, colBase = blockIdx.x * 128;

    float acc[8][8];
    #pragma unroll
    for (int r = 0; r < 8; r++)
        #pragma unroll
        for (int c = 0; c < 8; c++) acc[r][c] = 0.0f;

    #pragma unroll
    for (int ph = 0; ph < 2; ph++) {
        if (ph) __syncthreads();
        #pragma unroll
        for (int k2 = 0; k2 < 4; k2++) {
            int idx = t + 256 * k2;
            int rid = idx >> 3;
            int d4 = (idx & 7) << 2;
            float4 v = *(const float4*)(x + (size_t)(rowBase + rid) * DD + ph * CT_KH + d4);
            xs[(d4 + 0) * CT_STRIDE + rid] = v.x;
            xs[(d4 + 1) * CT_STRIDE + rid] = v.y;
            xs[(d4 + 2) * CT_STRIDE + rid] = v.z;
            xs[(d4 + 3) * CT_STRIDE + rid] = v.w;
        }
        #pragma unroll
        for (int k2 = 0; k2 < 4; k2++) {
            int idx = t + 256 * k2;
            int cid = idx >> 3;
            int d4 = (idx & 7) << 2;
            float4 v = *(const float4*)(y + (size_t)(colBase + cid) * DD + ph * CT_KH + d4);
            ys[(d4 + 0) * CT_STRIDE + cid] = v.x;
            ys[(d4 + 1) * CT_STRIDE + cid] = v.y;
            ys[(d4 + 2) * CT_STRIDE + cid] = v.z;
            ys[(d4 + 3) * CT_STRIDE + cid] = v.w;
        }
        __syncthreads();

        #pragma unroll 8
        for (int d = 0; d < CT_KH; d++) {
            const float* xr = xs + d * CT_STRIDE;
            const float* yc = ys + d * CT_STRIDE;
            float4 a0 = *(const float4*)(xr + (ty << 2));
            float4 a1 = *(const float4*)(xr + (ty << 2) + 64);
            float4 b0 = *(const float4*)(yc + (tx << 2));
            float4 b1 = *(const float4*)(yc + (tx << 2) + 64);
            float av[8] = {a0.x, a0.y, a0.z, a0.w, a1.x, a1.y, a1.z, a1.w};
            float bv[8] = {b0.x, b0.y, b0.z, b0.w, b1.x, b1.y, b1.z, b1.w};
            #pragma unroll
            for (int r = 0; r < 8; r++)
                #pragma unroll
                for (int c = 0; c < 8; c++)
                    acc[r][c] = fmaf(av[r], bv[c], acc[r][c]);
        }
    }

    float4 nyA = *(const float4*)(d_ny + colBase + (tx << 2));
    float4 nyB = *(const float4*)(d_ny + colBase + (tx << 2) + 64);
    #pragma unroll
    for (int rg = 0; rg < 2; rg++) {
        #pragma unroll
        for (int r4 = 0; r4 < 4; r4++) {
            int r = rg * 4 + r4;
            int row = rowBase + (ty << 2) + rg * 64 + r4;
            float nxr = d_nx[row];
            float4 oA, oB;
            oA.x = nxr + nyA.x - 2.0f * acc[r][0];
            oA.y = nxr + nyA.y - 2.0f * acc[r][1];
            oA.z = nxr + nyA.z - 2.0f * acc[r][2];
            oA.w = nxr + nyA.w - 2.0f * acc[r][3];
            oB.x = nxr + nyB.x - 2.0f * acc[r][4];
            oB.y = nxr + nyB.y - 2.0f * acc[r][5];
            oB.z = nxr + nyB.z - 2.0f * acc[r][6];
            oB.w = nxr + nyB.w - 2.0f * acc[r][7];
            float* dst = d_C + (size_t)row * MM + colBase + (tx << 2);
            *(float4*)dst = oA;
            *(float4*)(dst + 64) = oB;
        }
    }
}

// ====== iter-1 exact row pass (g=0) ======
__global__ void __launch_bounds__(256)
k_row(const float* __restrict__ p) {
    __shared__ float s_pm[16], s_ps[16];
    const int t = threadIdx.x;
    const int lane = t & 31;
    const int warp = t >> 5;
    const int r0 = blockIdx.x * 2;
    const float* C0 = d_C + (size_t)r0 * MM;
    const float* C1 = C0 + MM;

    float4 v0[4], v1[4];
    #pragma unroll
    for (int w = 0; w < 4; w++) {
        int j = (t + 256 * w) * 4;
        float4 g4 = *(const float4*)(d_g + j);
        float4 c0 = *(const float4*)(C0 + j);
        float4 c1 = *(const float4*)(C1 + j);
        v0[w] = f4sub(g4, c0);
        v1[w] = f4sub(g4, c1);
    }
    float m0 = fmaxf(fmaxf(f4max(v0[0]), f4max(v0[1])), fmaxf(f4max(v0[2]), f4max(v0[3])));
    float m1 = fmaxf(fmaxf(f4max(v1[0]), f4max(v1[1])), fmaxf(f4max(v1[2]), f4max(v1[3])));
    float s0 = f4expsum(v0[0], m0) + f4expsum(v0[1], m0) + f4expsum(v0[2], m0) + f4expsum(v0[3], m0);
    float s1 = f4expsum(v1[0], m1) + f4expsum(v1[1], m1) + f4expsum(v1[2], m1) + f4expsum(v1[3], m1);

    #pragma unroll
    for (int o = 16; o; o >>= 1) {
        float mo = __shfl_down_sync(0xffffffffu, m0, o);
        float so = __shfl_down_sync(0xffffffffu, s0, o);
        lse_merge(m0, s0, mo, so);
        mo = __shfl_down_sync(0xffffffffu, m1, o);
        so = __shfl_down_sync(0xffffffffu, s1, o);
        lse_merge(m1, s1, mo, so);
    }
    if (lane == 0) {
        s_pm[warp] = m0;     s_ps[warp] = s0;
        s_pm[8 + warp] = m1; s_ps[8 + warp] = s1;
    }
    __syncthreads();
    if (warp == 0) {
        float mm = s_pm[lane & 15], ss = s_ps[lane & 15];
        #pragma unroll
        for (int o = 4; o; o >>= 1) {
            float mo = __shfl_down_sync(0xffffffffu, mm, o, 8);
            float so = __shfl_down_sync(0xffffffffu, ss, o, 8);
            lse_merge(mm, ss, mo, so);
        }
        if (lane == 0) d_f[r0]     = W_EPS * __logf(p[r0])     - mm - W_EPS * __logf(ss);
        if (lane == 8) d_f[r0 + 1] = W_EPS * __logf(p[r0 + 1]) - mm - W_EPS * __logf(ss);
    }
}

// ====== plain-sum row pass (iters 2..10): T_i = sum_j exp((f+g-C)/eps) <= 1 ======
__global__ void __launch_bounds__(256)
k_rowsum(const float* __restrict__ p) {
    __shared__ float s_s[16];
    const int t = threadIdx.x;
    const int lane = t & 31;
    const int warp = t >> 5;
    const int r0 = blockIdx.x * 2;
    const float* C0 = d_C + (size_t)r0 * MM;
    const float* C1 = C0 + MM;
    const float f0 = d_f[r0], f1 = d_f[r0 + 1];

    float s0 = 0.0f, s1 = 0.0f;
    #pragma unroll
    for (int w = 0; w < 4; w++) {
        int j = (t + 256 * w) * 4;
        float4 g4 = *(const float4*)(d_g + j);
        float4 c0 = *(const float4*)(C0 + j);
        float4 c1 = *(const float4*)(C1 + j);
        s0 += __expf((f0 + g4.x - c0.x) * INV_EPS) + __expf((f0 + g4.y - c0.y) * INV_EPS)
            + __expf((f0 + g4.z - c0.z) * INV_EPS) + __expf((f0 + g4.w - c0.w) * INV_EPS);
        s1 += __expf((f1 + g4.x - c1.x) * INV_EPS) + __expf((f1 + g4.y - c1.y) * INV_EPS)
            + __expf((f1 + g4.z - c1.z) * INV_EPS) + __expf((f1 + g4.w - c1.w) * INV_EPS);
    }
    #pragma unroll
    for (int o = 16; o; o >>= 1) {
        s0 += __shfl_xor_sync(0xffffffffu, s0, o);
        s1 += __shfl_xor_sync(0xffffffffu, s1, o);
    }
    if (lane == 0) { s_s[warp] = s0; s_s[8 + warp] = s1; }
    __syncthreads();
    if (warp == 0 && lane < 2) {
        float T = s_s[lane * 8 + 0] + s_s[lane * 8 + 1] + s_s[lane * 8 + 2] + s_s[lane * 8 + 3]
                + s_s[lane * 8 + 4] + s_s[lane * 8 + 5] + s_s[lane * 8 + 6] + s_s[lane * 8 + 7];
        float fo = (lane == 0) ? f0 : f1;
        d_f[r0 + lane] = fo + W_EPS * __logf(p[r0 + lane]) - W_EPS * __logf(T);
    }
}

// ====== exact column pass (iteration 1 only) ======
__global__ void __launch_bounds__(256)
k_colpart() {
    const int lane = threadIdx.x & 31;
    const int warp = threadIdx.x >> 5;
    const int u = blockIdx.x * 8 + warp;
    const int slab = u >> 7;
    const int col = ((u & 127) << 5) + lane;
    const float* Cp = d_C + (size_t)slab * RPS * MM + col;
    const float* fp = d_f + slab * RPS;

    float m0 = -3.4e38f, s0 = 0.0f, m1 = -3.4e38f, s1 = 0.0f;
    float m2 = -3.4e38f, s2 = 0.0f, m3 = -3.4e38f, s3 = 0.0f;
    #pragma unroll 8
    for (int k = 0; k < RPS / 4; k++) {
        int r = k * 4;
        float c0 = Cp[(size_t)(r + 0) * MM];
        float c1 = Cp[(size_t)(r + 1) * MM];
        float c2 = Cp[(size_t)(r + 2) * MM];
        float c3 = Cp[(size_t)(r + 3) * MM];
        lse_upd1(m0, s0, fp[r + 0] - c0);
        lse_upd1(m1, s1, fp[r + 1] - c1);
        lse_upd1(m2, s2, fp[r + 2] - c2);
        lse_upd1(m3, s3, fp[r + 3] - c3);
    }
    lse_merge(m0, s0, m1, s1);
    lse_merge(m2, s2, m3, s3);
    lse_merge(m0, s0, m2, s2);
    d_pm[slab * MM + col] = m0;
    d_ps[slab * MM + col] = s0;
}

__global__ void __launch_bounds__(256)
k_colfin(const float* __restrict__ q) {
    int j = blockIdx.x * 256 + threadIdx.x;
    float m0 = -3.4e38f, s0 = 0.0f, m1 = -3.4e38f, s1 = 0.0f;
    float m2 = -3.4e38f, s2 = 0.0f, m3 = -3.4e38f, s3 = 0.0f;
    #pragma unroll
    for (int k = 0; k < SLABS / 4; k++) {
        int k4 = k * 4;
        lse_merge(m0, s0, d_pm[(k4 + 0) * MM + j], d_ps[(k4 + 0) * MM + j]);
        lse_merge(m1, s1, d_pm[(k4 + 1) * MM + j], d_ps[(k4 + 1) * MM + j]);
        lse_merge(m2, s2, d_pm[(k4 + 2) * MM + j], d_ps[(k4 + 2) * MM + j]);
        lse_merge(m3, s3, d_pm[(k4 + 3) * MM + j], d_ps[(k4 + 3) * MM + j]);
    }
    lse_merge(m0, s0, m1, s1);
    lse_merge(m2, s2, m3, s3);
    lse_merge(m0, s0, m2, s2);
    d_g[j] = W_EPS * __logf(q[j]) - m0 - W_EPS * __logf(s0);
}

// ====== plain-sum column pass (iterations 2..10) ======
__global__ void __launch_bounds__(256)
k_colsum() {
    const int lane = threadIdx.x & 31;
    const int warp = threadIdx.x >> 5;
    const int u = blockIdx.x * 8 + warp;
    const int slab = u >> 7;
    const int col = ((u & 127) << 5) + lane;
    const float* Cp = d_C + (size_t)slab * RPS * MM + col;
    const float* fp = d_f + slab * RPS;
    const float gj = d_g[col];

    float a0 = 0.0f, a1 = 0.0f, a2 = 0.0f, a3 = 0.0f;
    #pragma unroll 8
    for (int k = 0; k < RPS / 4; k++) {
        int r = k * 4;
        float c0 = Cp[(size_t)(r + 0) * MM];
        float c1 = Cp[(size_t)(r + 1) * MM];
        float c2 = Cp[(size_t)(r + 2) * MM];
        float c3 = Cp[(size_t)(r + 3) * MM];
        a0 += __expf((fp[r + 0] + gj - c0) * INV_EPS);
        a1 += __expf((fp[r + 1] + gj - c1) * INV_EPS);
        a2 += __expf((fp[r + 2] + gj - c2) * INV_EPS);
        a3 += __expf((fp[r + 3] + gj - c3) * INV_EPS);
    }
    d_ps[slab * MM + col] = (a0 + a1) + (a2 + a3);
}

__global__ void __launch_bounds__(256)
k_colfin2(const float* __restrict__ q) {
    int j = blockIdx.x * 256 + threadIdx.x;
    float a0 = 0.0f, a1 = 0.0f, a2 = 0.0f, a3 = 0.0f;
    #pragma unroll
    for (int k = 0; k < SLABS / 4; k++) {
        int k4 = k * 4;
        a0 += d_ps[(k4 + 0) * MM + j];
        a1 += d_ps[(k4 + 1) * MM + j];
        a2 += d_ps[(k4 + 2) * MM + j];
        a3 += d_ps[(k4 + 3) * MM + j];
    }
    float A = (a0 + a1) + (a2 + a3);
    d_g[j] = W_EPS * __logf(q[j]) + d_g[j] - W_EPS * __logf(A);
}

// ================= final: P = exp(S), cost partials =================
__global__ void __launch_bounds__(256)
k_final(float* __restrict__ Pout, int writeP) {
    __shared__ double dred[8];
    const int gsz = 2048 * 256;
    const int gtid = blockIdx.x * 256 + threadIdx.x;
    const int NV4 = (NN * MM) / 4;
    double csum = 0.0;
    #pragma unroll 4
    for (int v4 = gtid; v4 < NV4; v4 += gsz) {
        int base = v4 * 4;
        int i = base >> 12;
        int j = base & (MM - 1);
        float4 c4 = *(const float4*)(d_C + (size_t)base);
        float fi = d_f[i];
        float4 g4 = *(const float4*)(d_g + j);
        float p0 = __expf((fi + g4.x - c4.x) * INV_EPS);
        float p1 = __expf((fi + g4.y - c4.y) * INV_EPS);
        float p2 = __expf((fi + g4.z - c4.z) * INV_EPS);
        float p3 = __expf((fi + g4.w - c4.w) * INV_EPS);
        if (writeP) {
            Pout[base + 0] = p0; Pout[base + 1] = p1;
            Pout[base + 2] = p2; Pout[base + 3] = p3;
        }
        csum += (double)(p0 * c4.x + p1 * c4.y + p2 * c4.z + p3 * c4.w);
    }
    #pragma unroll
    for (int o = 16; o; o >>= 1) csum += __shfl_xor_sync(0xffffffffu, csum, o);
    if ((threadIdx.x & 31) == 0) dred[threadIdx.x >> 5] = csum;
    __syncthreads();
    if (threadIdx.x == 0) {
        double sb = 0.0;
        #pragma unroll
        for (int k2 = 0; k2 < 8; k2++) sb += dred[k2];
        d_parts[blockIdx.x] = sb;
    }
}

__global__ void k_costfin(float* __restrict__ costslot) {
    __shared__ double fin[256];
    int t = threadIdx.x;
    double s = 0.0;
    for (int k2 = t; k2 < 2048; k2 += 256) s += d_parts[k2];
    fin[t] = s;
    __syncthreads();
    if (t == 0) {
        double tot = 0.0;
        for (int k2 = 0; k2 < 256; k2++) tot += fin[k2];
        costslot[0] = (float)tot;
    }
}

// ================= host launch =================
extern "C" void kernel_launch(void* const* d_in, const int* in_sizes, int n_in,
                              void* d_out, int out_size) {
    const float* x = (const float*)d_in[0];
    const float* y = (const float*)d_in[1];
    const float* p = (const float*)d_in[2];
    const float* q = (const float*)d_in[3];
    (void)in_sizes; (void)n_in;

    float* out = (float*)d_out;
    float* costslot = nullptr;
    float* Pout = nullptr;
    const long long total = (long long)NN * MM;
    if ((long long)out_size >= total + 1) { costslot = out; Pout = out + 1; }
    else if ((long long)out_size >= total) { Pout = out; }
    else { costslot = out; }

    k_prep<<<1024, 256>>>(x, y);
    k_cost<<<dim3(MM / 128, NN / 128), 256>>>(x, y);

    // iteration 1: exact two-pass (g = 0)
    k_row<<<NN / 2, 256>>>(p);
    k_colpart<<<512, 256>>>();
    k_colfin<<<16, 256>>>(q);

    // iterations 2..10: plain-sum row + column passes
    for (int it = 1; it < ITERS; it++) {
        k_rowsum<<<NN / 2, 256>>>(p);
        k_colsum<<<512, 256>>>();
        k_colfin2<<<16, 256>>>(q);
    }

    k_final<<<2048, 256>>>(Pout, Pout != nullptr);
    if (costslot) k_costfin<<<1, 256>>>(costslot);
}